// round 8
// baseline (speedup 1.0000x reference)
#include <cuda_runtime.h>
#include <cuda_bf16.h>
#include <cstdint>

// Shapes (fixed by the problem)
#define B_   32
#define H_   8
#define C_   64
#define L_   1024
#define HC_  512          // H_*C_
#define K_   6            // int(log(1024)) = 6
#define QP_  4            // partial quarters per batch (128 rows each)

// k_agg tiling
#define TROWS 2           // rows per block (16KB smem with duplication)

// Scratch (no allocations allowed -> __device__ globals)
__device__ float g_partial[B_ * QP_ * L_];  // 512 KB
__device__ int   g_idx[K_];
__device__ float g_wts[B_ * K_];

// ---------------------------------------------------------------------------
// Kernel 1: partial reduce of corr. grid (B_, QP_) = 128 blocks (single wave),
// 256 threads; block sums 128 rows with float4 + 8 accumulators (MLP=8).
// ---------------------------------------------------------------------------
__global__ __launch_bounds__(256) void k_partial(const float* __restrict__ corr) {
    const int b = blockIdx.x;
    const int q = blockIdx.y;
    const int t = threadIdx.x;
    const float4* __restrict__ base =
        reinterpret_cast<const float4*>(corr) +
        ((size_t)b * HC_ + (size_t)q * 128) * (L_ / 4) + t;

    float4 acc[8];
#pragma unroll
    for (int m = 0; m < 8; ++m) acc[m] = make_float4(0.f, 0.f, 0.f, 0.f);

    for (int r = 0; r < 128; r += 8) {
#pragma unroll
        for (int m = 0; m < 8; ++m) {
            float4 v = base[(size_t)(r + m) * (L_ / 4)];
            acc[m].x += v.x; acc[m].y += v.y; acc[m].z += v.z; acc[m].w += v.w;
        }
    }
    // pairwise combine
#pragma unroll
    for (int m = 0; m < 4; ++m) {
        acc[m].x += acc[m + 4].x; acc[m].y += acc[m + 4].y;
        acc[m].z += acc[m + 4].z; acc[m].w += acc[m + 4].w;
    }
#pragma unroll
    for (int m = 0; m < 2; ++m) {
        acc[m].x += acc[m + 2].x; acc[m].y += acc[m + 2].y;
        acc[m].z += acc[m + 2].z; acc[m].w += acc[m + 2].w;
    }
    float4 s;
    s.x = acc[0].x + acc[1].x; s.y = acc[0].y + acc[1].y;
    s.z = acc[0].z + acc[1].z; s.w = acc[0].w + acc[1].w;
    reinterpret_cast<float4*>(g_partial)[((size_t)(b * QP_ + q)) * (L_ / 4) + t] = s;
}

// ---------------------------------------------------------------------------
// Kernel 2: single block, 1024 threads. Combine partials (ranking criterion =
// column sum, monotone to the mean), top-6 via argmax-iterate with
// smaller-index tie-break (same SET as lax.top_k; order irrelevant because the
// softmax-weighted sum is permutation invariant), then per-batch softmax.
// ---------------------------------------------------------------------------
__global__ __launch_bounds__(1024) void k_topk_softmax() {
    __shared__ float sm[L_];
    __shared__ float wval[32];
    __shared__ int   widx[32];
    __shared__ int   s_idx[K_];

    const int t   = threadIdx.x;     // == l
    const int wid = t >> 5;
    const int lid = t & 31;

    // combine 128 partials per column (from L2)
    {
        float s = 0.f;
#pragma unroll 8
        for (int i = 0; i < B_ * QP_; ++i)
            s += g_partial[(size_t)i * L_ + t];
        sm[t] = s;
    }
    __syncthreads();

    for (int k = 0; k < K_; ++k) {
        float bv = sm[t];
        int   bi = t;
#pragma unroll
        for (int off = 16; off > 0; off >>= 1) {
            float v2 = __shfl_down_sync(0xffffffffu, bv, off);
            int   i2 = __shfl_down_sync(0xffffffffu, bi, off);
            if (v2 > bv || (v2 == bv && i2 < bi)) { bv = v2; bi = i2; }
        }
        if (lid == 0) { wval[wid] = bv; widx[wid] = bi; }
        __syncthreads();
        if (t == 0) {
            float fv = wval[0]; int fi = widx[0];
#pragma unroll
            for (int w = 1; w < 32; ++w) {
                if (wval[w] > fv || (wval[w] == fv && widx[w] < fi)) {
                    fv = wval[w]; fi = widx[w];
                }
            }
            s_idx[k] = fi;
            g_idx[k] = fi;
            sm[fi]   = -3.0e38f;
        }
        __syncthreads();
    }

    // per-batch softmax over mean_value[b, idx[0..5]]
    if (t < B_) {
        const int b = t;
        float w[K_];
        float m = -3.0e38f;
#pragma unroll
        for (int k = 0; k < K_; ++k) {
            const int idx = s_idx[k];
            float p = 0.f;
#pragma unroll
            for (int q = 0; q < QP_; ++q)
                p += g_partial[(size_t)(b * QP_ + q) * L_ + idx];
            w[k] = p * (1.0f / (float)HC_);
            m = fmaxf(m, w[k]);
        }
        float sum = 0.f;
#pragma unroll
        for (int k = 0; k < K_; ++k) { w[k] = __expf(w[k] - m); sum += w[k]; }
        const float inv = 1.0f / sum;
#pragma unroll
        for (int k = 0; k < K_; ++k) g_wts[b * K_ + k] = w[k] * inv;
    }
}

// ---------------------------------------------------------------------------
// Kernel 3: delays aggregation, instruction-minimal inner loop.
// Each row is staged DUPLICATED in smem (sv[x] = sv[x+L] = row[x]) so the
// circular index (l+i)&1023 becomes a plain s[l+i]: no AND, no per-access
// IADD. Six base pointers (srow + i_k + t) are hoisted per row; the inner
// loop is pure LDS [ptr + imm] + FFMA + one coalesced STG per j.
// LDS stride-1 across lanes -> conflict-free.
// ---------------------------------------------------------------------------
__global__ __launch_bounds__(256) void k_agg(const float* __restrict__ values,
                                             float* __restrict__ out) {
    __shared__ float sv[TROWS * 2 * L_];    // 16 KB
    const int t    = threadIdx.x;
    const int row0 = blockIdx.x * TROWS;
    const int b    = row0 >> 9;             // row0 / (H_*C_)

    // stage TROWS rows, duplicated
    const float4* __restrict__ src =
        reinterpret_cast<const float4*>(values + (size_t)row0 * L_);
    float4* sv4 = reinterpret_cast<float4*>(sv);
#pragma unroll
    for (int r = 0; r < TROWS; ++r) {
        float4 v = src[r * 256 + t];
        sv4[r * 512 + t]       = v;
        sv4[r * 512 + 256 + t] = v;
    }

    // broadcast weights + indices (L2-resident)
    const float w0 = g_wts[b * K_ + 0], w1 = g_wts[b * K_ + 1], w2 = g_wts[b * K_ + 2];
    const float w3 = g_wts[b * K_ + 3], w4 = g_wts[b * K_ + 4], w5 = g_wts[b * K_ + 5];
    const int   i0 = g_idx[0], i1 = g_idx[1], i2 = g_idx[2];
    const int   i3 = g_idx[3], i4 = g_idx[4], i5 = g_idx[5];

    __syncthreads();

#pragma unroll
    for (int r = 0; r < TROWS; ++r) {
        const float* srow = sv + r * 2 * L_;
        const float* p0 = srow + i0 + t;
        const float* p1 = srow + i1 + t;
        const float* p2 = srow + i2 + t;
        const float* p3 = srow + i3 + t;
        const float* p4 = srow + i4 + t;
        const float* p5 = srow + i5 + t;
        float* drow = out + (size_t)(row0 + r) * L_;
#pragma unroll
        for (int j = 0; j < 4; ++j) {
            const int off = j * 256;
            float acc;
            acc  = p0[off] * w0;
            acc += p1[off] * w1;
            acc += p2[off] * w2;
            acc += p3[off] * w3;
            acc += p4[off] * w4;
            acc += p5[off] * w5;
            drow[t + off] = acc;
        }
    }
}

// ---------------------------------------------------------------------------
extern "C" void kernel_launch(void* const* d_in, const int* in_sizes, int n_in,
                              void* d_out, int out_size) {
    const float* values = (const float*)d_in[0];
    const float* corr   = (const float*)d_in[1];
    float*       out    = (float*)d_out;

    dim3 g1(B_, QP_);
    k_partial<<<g1, 256>>>(corr);
    k_topk_softmax<<<1, 1024>>>();
    k_agg<<<(B_ * H_ * C_) / TROWS, 256>>>(values, out);
}